// round 2
// baseline (speedup 1.0000x reference)
#include <cuda_runtime.h>
#include <cuda_bf16.h>
#include <math.h>

// Problem constants
#define D_DIM   2048
#define KEMB    16384
#define NPIX    8192                 // 8 * 32 * 32
#define QUANT_ELEMS (8 * 2048 * 32 * 32)   // 16,777,216

// Scratch (static __device__ globals — no runtime allocation allowed)
__device__ float g_e_n[(size_t)KEMB * D_DIM];          // normalized codebook, 134 MB
__device__ float g_zT[(size_t)NPIX * D_DIM];           // transposed hidden (raw, unnormalized), 67 MB
__device__ unsigned long long g_key[NPIX];             // packed (enc(sim)<<32)|(~idx)

// Monotonic float->uint encoding (order-preserving for all finite floats)
__device__ __forceinline__ unsigned enc_f(float f) {
    unsigned u = __float_as_uint(f);
    return (u & 0x80000000u) ? ~u : (u | 0x80000000u);
}

// ---------------------------------------------------------------------------
// Kernel 0: clear argmax keys.
// ---------------------------------------------------------------------------
__global__ void init_keys_kernel() {
    int n = blockIdx.x * 256 + threadIdx.x;
    if (n < NPIX) g_key[n] = 0ull;
}

// ---------------------------------------------------------------------------
// Kernel 1: L2-normalize codebook rows. grid=KEMB, block=256.
// ---------------------------------------------------------------------------
__global__ void normalize_e_kernel(const float* __restrict__ E) {
    const int r = blockIdx.x;
    const int tid = threadIdx.x;
    const float4* src = reinterpret_cast<const float4*>(E + (size_t)r * D_DIM);
    float4* dst = reinterpret_cast<float4*>(g_e_n + (size_t)r * D_DIM);

    float4 v0 = src[tid];
    float4 v1 = src[tid + 256];
    float s = v0.x*v0.x + v0.y*v0.y + v0.z*v0.z + v0.w*v0.w
            + v1.x*v1.x + v1.y*v1.y + v1.z*v1.z + v1.w*v1.w;

    __shared__ float red[8];
    #pragma unroll
    for (int o = 16; o; o >>= 1) s += __shfl_xor_sync(0xffffffffu, s, o);
    if ((tid & 31) == 0) red[tid >> 5] = s;
    __syncthreads();
    if (tid == 0) {
        float t = 0.f;
        #pragma unroll
        for (int i = 0; i < 8; i++) t += red[i];
        red[0] = 1.0f / fmaxf(sqrtf(t), 1e-12f);   // matches max(||x||, eps)
    }
    __syncthreads();
    const float sc = red[0];
    dst[tid]       = make_float4(v0.x*sc, v0.y*sc, v0.z*sc, v0.w*sc);
    dst[tid + 256] = make_float4(v1.x*sc, v1.y*sc, v1.z*sc, v1.w*sc);
}

// ---------------------------------------------------------------------------
// Kernel 2: transpose hidden (B,C,H,W)->(N,D) row-major.
// grid = 256 (one block per (b,h)), block = 256.
// ---------------------------------------------------------------------------
__global__ void prep_z_kernel(const float* __restrict__ X) {
    const int b = blockIdx.x >> 5;
    const int h = blockIdx.x & 31;
    const int tid = threadIdx.x;
    const int w = tid & 31;       // lane
    const int q = tid >> 5;       // warp 0..7
    __shared__ float tile[32][33];
    const int base_n = (b * 32 + h) * 32;

    for (int c0 = 0; c0 < D_DIM; c0 += 32) {
        #pragma unroll
        for (int j = 0; j < 4; j++) {
            int c = c0 + q + 8 * j;
            // fixed c per instruction, lanes sweep w -> 128B coalesced
            tile[q + 8 * j][w] = X[(((size_t)b * D_DIM + c) * 32 + h) * 32 + w];
        }
        __syncthreads();
        #pragma unroll
        for (int j = 0; j < 4; j++) {
            int y = q + 8 * j;   // pixel w-coordinate
            // lanes sweep channel -> coalesced row-major writes; tile[w][y] pad-33 conflict-free
            g_zT[(size_t)(base_n + y) * D_DIM + c0 + w] = tile[w][y];
        }
        __syncthreads();
    }
}

// ---------------------------------------------------------------------------
// Kernel 3: fused SGEMM (z_raw . e_n^T) + per-row argmax via packed atomicMax.
// Tiles: BM=128 (pixels) x BN=128 (codes) x BK=8, 256 threads, 8x8 per thread.
// grid = (KEMB/128, NPIX/128) = (128, 64).
// ---------------------------------------------------------------------------
__global__ __launch_bounds__(256, 2)
void sgemm_argmax_kernel() {
    __shared__ __align__(16) float As[2][8][128];
    __shared__ __align__(16) float Bs[2][8][128];
    __shared__ float sval[128][17];
    __shared__ int   sidx[128][17];

    const int tid = threadIdx.x;
    const int bn = blockIdx.x;            // code tile
    const int bm = blockIdx.y;            // pixel tile
    const float* __restrict__ zb = g_zT  + (size_t)bm * 128 * D_DIM;
    const float* __restrict__ eb = g_e_n + (size_t)bn * 128 * D_DIM;

    const int lrow = tid >> 1;            // 0..127
    const int lc4  = (tid & 1) << 2;      // 0 or 4

    // prologue: load k-slab 0
    float4 aR = *reinterpret_cast<const float4*>(zb + (size_t)lrow * D_DIM + lc4);
    float4 bR = *reinterpret_cast<const float4*>(eb + (size_t)lrow * D_DIM + lc4);
    As[0][lc4+0][lrow] = aR.x; As[0][lc4+1][lrow] = aR.y;
    As[0][lc4+2][lrow] = aR.z; As[0][lc4+3][lrow] = aR.w;
    Bs[0][lc4+0][lrow] = bR.x; Bs[0][lc4+1][lrow] = bR.y;
    Bs[0][lc4+2][lrow] = bR.z; Bs[0][lc4+3][lrow] = bR.w;
    __syncthreads();

    float acc[8][8] = {};
    const int tx = tid & 15, ty = tid >> 4;
    const int mBase = ty * 8, nBase = tx * 8;

    #pragma unroll 1
    for (int kt = 0; kt < 256; kt++) {
        const int cur = kt & 1;
        if (kt < 255) {
            int c = (kt + 1) * 8 + lc4;
            aR = *reinterpret_cast<const float4*>(zb + (size_t)lrow * D_DIM + c);
            bR = *reinterpret_cast<const float4*>(eb + (size_t)lrow * D_DIM + c);
        }
        #pragma unroll
        for (int k = 0; k < 8; k++) {
            float a[8], b[8];
            *reinterpret_cast<float4*>(a)     = *reinterpret_cast<const float4*>(&As[cur][k][mBase]);
            *reinterpret_cast<float4*>(a + 4) = *reinterpret_cast<const float4*>(&As[cur][k][mBase + 4]);
            *reinterpret_cast<float4*>(b)     = *reinterpret_cast<const float4*>(&Bs[cur][k][nBase]);
            *reinterpret_cast<float4*>(b + 4) = *reinterpret_cast<const float4*>(&Bs[cur][k][nBase + 4]);
            #pragma unroll
            for (int i = 0; i < 8; i++)
                #pragma unroll
                for (int j = 0; j < 8; j++)
                    acc[i][j] += a[i] * b[j];
        }
        if (kt < 255) {
            const int nxt = cur ^ 1;
            As[nxt][lc4+0][lrow] = aR.x; As[nxt][lc4+1][lrow] = aR.y;
            As[nxt][lc4+2][lrow] = aR.z; As[nxt][lc4+3][lrow] = aR.w;
            Bs[nxt][lc4+0][lrow] = bR.x; Bs[nxt][lc4+1][lrow] = bR.y;
            Bs[nxt][lc4+2][lrow] = bR.z; Bs[nxt][lc4+3][lrow] = bR.w;
            __syncthreads();
        }
    }

    // Epilogue: per-thread 8-col argmax (strict > keeps smallest j = first occurrence)
    #pragma unroll
    for (int i = 0; i < 8; i++) {
        float bv = acc[i][0]; int bj = 0;
        #pragma unroll
        for (int j = 1; j < 8; j++)
            if (acc[i][j] > bv) { bv = acc[i][j]; bj = j; }
        sval[mBase + i][tx] = bv;
        sidx[mBase + i][tx] = nBase + bj;
    }
    __syncthreads();

    if (tid < 128) {
        float bv = sval[tid][0]; int bi = sidx[tid][0];
        #pragma unroll
        for (int j = 1; j < 16; j++) {
            float v = sval[tid][j]; int id = sidx[tid][j];
            if (v > bv || (v == bv && id < bi)) { bv = v; bi = id; }
        }
        const unsigned gcol = (unsigned)(bn * 128 + bi);
        const unsigned long long kk =
            ((unsigned long long)enc_f(bv) << 32) |
            (unsigned long long)(0xFFFFFFFFu - gcol);   // tie -> smaller index wins
        atomicMax(&g_key[(size_t)bm * 128 + tid], kk);
    }
}

// ---------------------------------------------------------------------------
// Kernel 4: gather quant = e_n[idx] back to (B,C,H,W); optional idx tail.
// grid = 256 (one block per (b,h)), block = 256.
// ---------------------------------------------------------------------------
__global__ void gather_kernel(float* __restrict__ out, int write_idx_tail) {
    const int b = blockIdx.x >> 5;
    const int h = blockIdx.x & 31;
    const int tid = threadIdx.x;
    const int w = tid & 31;
    const int q = tid >> 5;
    __shared__ int rowidx[32];
    __shared__ float tile[32][33];

    if (tid < 32) {
        int n = (b * 32 + h) * 32 + tid;
        unsigned long long kk = g_key[n];
        int id = (int)(0xFFFFFFFFu - (unsigned)(kk & 0xFFFFFFFFu));
        rowidx[tid] = id;
        if (write_idx_tail) out[QUANT_ELEMS + n] = (float)id;
    }
    __syncthreads();

    for (int c0 = 0; c0 < D_DIM; c0 += 32) {
        #pragma unroll
        for (int j = 0; j < 4; j++) {
            int c = c0 + q + 8 * j;
            tile[q + 8 * j][w] = g_e_n[(size_t)rowidx[w] * D_DIM + c];
        }
        __syncthreads();
        #pragma unroll
        for (int j = 0; j < 4; j++) {
            int c = c0 + q + 8 * j;
            out[(((size_t)b * D_DIM + c) * 32 + h) * 32 + w] = tile[q + 8 * j][w];
        }
        __syncthreads();
    }
}

// Fallback if the harness output is just idx (int32)
__global__ void idx_only_kernel(int* __restrict__ out) {
    int n = blockIdx.x * 256 + threadIdx.x;
    if (n < NPIX)
        out[n] = (int)(0xFFFFFFFFu - (unsigned)(g_key[n] & 0xFFFFFFFFu));
}

// ---------------------------------------------------------------------------
extern "C" void kernel_launch(void* const* d_in, const int* in_sizes, int n_in,
                              void* d_out, int out_size) {
    const float* hidden = (const float*)d_in[0];
    const float* embed  = (const float*)d_in[1];
    // Defensive: distinguish by element count (hidden=16.7M, embedding=33.5M)
    if (n_in >= 2 && in_sizes[0] == KEMB * D_DIM) {
        const float* t = hidden; hidden = embed; embed = t;
    }

    init_keys_kernel<<<(NPIX + 255) / 256, 256>>>();
    normalize_e_kernel<<<KEMB, 256>>>(embed);
    prep_z_kernel<<<256, 256>>>(hidden);

    dim3 grid(KEMB / 128, NPIX / 128);   // (128, 64)
    sgemm_argmax_kernel<<<grid, 256>>>();

    if (out_size == NPIX) {
        idx_only_kernel<<<(NPIX + 255) / 256, 256>>>((int*)d_out);
    } else {
        int tail = (out_size >= QUANT_ELEMS + NPIX) ? 1 : 0;
        gather_kernel<<<256, 256>>>((float*)d_out, tail);
    }
}

// round 6
// speedup vs baseline: 4.8808x; 4.8808x over previous
#include <cuda_runtime.h>
#include <cuda_bf16.h>
#include <math.h>
#include <stdint.h>

// ---------------- Problem constants ----------------
#define D_DIM   2048
#define KEMB    16384
#define NPIX    8192
#define QUANT_ELEMS (8 * 2048 * 32 * 32)

// ---------------- GEMM tiling ----------------
#define BM 128
#define BN 128
#define BK 32                    // bf16 elements of K per stage
#define ROWSTR 80                // padded smem row stride in bytes (64B data + 16B pad)
#define ATILE (128 * ROWSTR)     // 10240 B
#define STG_BYTES (2 * ATILE)    // 20480 B (A + B)
#define NSTAGE 3
#define GEMM_SMEM (NSTAGE * STG_BYTES)   // 61440 B

// ---------------- Device scratch (static globals; no runtime alloc) -------
__device__ __align__(16) __nv_bfloat16 g_A[(size_t)NPIX * D_DIM];   // bf16 z rows (raw)
__device__ __align__(16) __nv_bfloat16 g_B[(size_t)KEMB * D_DIM];   // bf16 normalized codebook
__device__ __align__(16) float         g_e_n[(size_t)KEMB * D_DIM]; // fp32 normalized codebook
__device__ __align__(16) float         g_zT[(size_t)NPIX * D_DIM];  // fp32 raw z rows
__device__ __align__(16) __nv_bfloat16 g_sim[(size_t)NPIX * KEMB];  // bf16 approx sims
__device__ int g_idx[NPIX];

// ---------------- helpers ----------------
__device__ __forceinline__ uint32_t smem_u32(const void* p) {
    uint32_t a;
    asm("{ .reg .u64 t; cvta.to.shared.u64 t, %1; cvt.u32.u64 %0, t; }" : "=r"(a) : "l"(p));
    return a;
}
__device__ __forceinline__ uint32_t pack_bf2(float a, float b) {
    __nv_bfloat162 h = __floats2bfloat162_rn(a, b);
    return *reinterpret_cast<uint32_t*>(&h);
}
__device__ __forceinline__ float bflo(uint32_t u) {
    unsigned short s = (unsigned short)(u & 0xffffu);
    return __bfloat162float(__ushort_as_bfloat16(s));
}
__device__ __forceinline__ float bfhi(uint32_t u) {
    unsigned short s = (unsigned short)(u >> 16);
    return __bfloat162float(__ushort_as_bfloat16(s));
}

#define CP_ASYNC16(dst, src) \
    asm volatile("cp.async.cg.shared.global [%0], [%1], 16;" :: "r"(dst), "l"(src) : "memory")
#define CP_COMMIT() asm volatile("cp.async.commit_group;" ::: "memory")
#define CP_WAIT(n)  asm volatile("cp.async.wait_group %0;" :: "n"(n) : "memory")

__device__ __forceinline__ void ldsm4(uint32_t* r, uint32_t addr) {
    asm volatile("ldmatrix.sync.aligned.m8n8.x4.shared.b16 {%0,%1,%2,%3}, [%4];"
        : "=r"(r[0]), "=r"(r[1]), "=r"(r[2]), "=r"(r[3]) : "r"(addr));
}
__device__ __forceinline__ void mma16816(float* c, const uint32_t* a, uint32_t b0, uint32_t b1) {
    asm volatile(
        "mma.sync.aligned.m16n8k16.row.col.f32.bf16.bf16.f32 "
        "{%0,%1,%2,%3}, {%4,%5,%6,%7}, {%8,%9}, {%0,%1,%2,%3};"
        : "+f"(c[0]), "+f"(c[1]), "+f"(c[2]), "+f"(c[3])
        : "r"(a[0]), "r"(a[1]), "r"(a[2]), "r"(a[3]), "r"(b0), "r"(b1));
}

// ---------------------------------------------------------------------------
// prep_e: normalize codebook row; write fp32 e_n and bf16 B (row-major).
// grid = KEMB, block = 256.
// ---------------------------------------------------------------------------
__global__ void prep_e_kernel(const float* __restrict__ E) {
    const int r = blockIdx.x, tid = threadIdx.x;
    const float4* src = reinterpret_cast<const float4*>(E + (size_t)r * D_DIM);
    float4* dst = reinterpret_cast<float4*>(g_e_n + (size_t)r * D_DIM);

    float4 v0 = src[2 * tid];
    float4 v1 = src[2 * tid + 1];
    float s = v0.x*v0.x + v0.y*v0.y + v0.z*v0.z + v0.w*v0.w
            + v1.x*v1.x + v1.y*v1.y + v1.z*v1.z + v1.w*v1.w;

    __shared__ float red[8];
    #pragma unroll
    for (int o = 16; o; o >>= 1) s += __shfl_xor_sync(0xffffffffu, s, o);
    if ((tid & 31) == 0) red[tid >> 5] = s;
    __syncthreads();
    if (tid == 0) {
        float t = 0.f;
        #pragma unroll
        for (int i = 0; i < 8; i++) t += red[i];
        red[0] = 1.0f / fmaxf(sqrtf(t), 1e-12f);
    }
    __syncthreads();
    const float sc = red[0];
    float4 w0 = make_float4(v0.x*sc, v0.y*sc, v0.z*sc, v0.w*sc);
    float4 w1 = make_float4(v1.x*sc, v1.y*sc, v1.z*sc, v1.w*sc);
    dst[2 * tid]     = w0;
    dst[2 * tid + 1] = w1;

    uint4 p;
    p.x = pack_bf2(w0.x, w0.y);
    p.y = pack_bf2(w0.z, w0.w);
    p.z = pack_bf2(w1.x, w1.y);
    p.w = pack_bf2(w1.z, w1.w);
    *reinterpret_cast<uint4*>(g_B + (size_t)r * D_DIM + tid * 8) = p;
}

// ---------------------------------------------------------------------------
// prep_z: transpose hidden (B,C,H,W)->(N,D); write fp32 zT and bf16 A rows.
// grid = 256 (one per (b,h)), block = 256.
// ---------------------------------------------------------------------------
__global__ void prep_z_kernel(const float* __restrict__ X) {
    const int b = blockIdx.x >> 5;
    const int h = blockIdx.x & 31;
    const int tid = threadIdx.x;
    const int w = tid & 31;
    const int q = tid >> 5;
    __shared__ float tile[32][33];
    const int base_n = (b * 32 + h) * 32;

    for (int c0 = 0; c0 < D_DIM; c0 += 32) {
        #pragma unroll
        for (int j = 0; j < 4; j++) {
            int ch = q + 8 * j;
            tile[ch][w] = X[(((size_t)b * D_DIM + c0 + ch) * 32 + h) * 32 + w];
        }
        __syncthreads();
        #pragma unroll
        for (int j = 0; j < 4; j++) {
            int y = q + 8 * j;
            g_zT[(size_t)(base_n + y) * D_DIM + c0 + w] = tile[w][y];
        }
        {
            const int px = tid >> 3;         // pixel-w 0..31
            const int g  = tid & 7;          // 4-channel group
            const int n  = base_n + px;
            uint2 p;
            p.x = pack_bf2(tile[g * 4 + 0][px], tile[g * 4 + 1][px]);
            p.y = pack_bf2(tile[g * 4 + 2][px], tile[g * 4 + 3][px]);
            *reinterpret_cast<uint2*>(g_A + (size_t)n * D_DIM + c0 + g * 4) = p;
        }
        __syncthreads();
    }
}

// ---------------------------------------------------------------------------
// GEMM: bf16 mma.sync, 128x128 tile per CTA, BK=32, 3-stage cp.async pipeline.
// grid = (64, 128), block = 256 (8 warps, 4(M) x 2(N), warp tile 32x64).
// Writes bf16 sims to g_sim [NPIX, KEMB].
// ---------------------------------------------------------------------------
__global__ void __launch_bounds__(256, 1) gemm_kernel() {
    extern __shared__ char smem[];
    const uint32_t sb = smem_u32(smem);
    const int tid = threadIdx.x;
    const int wid = tid >> 5;
    const int lane = tid & 31;
    const int mt = blockIdx.x;
    const int nt = blockIdx.y;

    const __nv_bfloat16* Ag = g_A + (size_t)mt * BM * D_DIM;
    const __nv_bfloat16* Bg = g_B + (size_t)nt * BN * D_DIM;
    const uint64_t AgG = __cvta_generic_to_global(Ag);
    const uint64_t BgG = __cvta_generic_to_global(Bg);

    // loader indices: 512 16B-chunks per tile; thread covers 2 chunks of A + 2 of B
    const int ch0 = tid, ch1 = tid + 256;
    const int r0 = ch0 >> 2, c0c = ch0 & 3;
    const int r1 = ch1 >> 2, c1c = ch1 & 3;

#define LOAD_STAGE(slot, kt) do {                                              \
    uint32_t dA = sb + (slot) * STG_BYTES;                                     \
    uint32_t dB = dA + ATILE;                                                  \
    uint64_t sA = AgG + ((size_t)(kt) * BK) * 2;                               \
    uint64_t sB = BgG + ((size_t)(kt) * BK) * 2;                               \
    CP_ASYNC16(dA + r0 * ROWSTR + c0c * 16, sA + (size_t)r0 * (D_DIM*2) + c0c * 16); \
    CP_ASYNC16(dA + r1 * ROWSTR + c1c * 16, sA + (size_t)r1 * (D_DIM*2) + c1c * 16); \
    CP_ASYNC16(dB + r0 * ROWSTR + c0c * 16, sB + (size_t)r0 * (D_DIM*2) + c0c * 16); \
    CP_ASYNC16(dB + r1 * ROWSTR + c1c * 16, sB + (size_t)r1 * (D_DIM*2) + c1c * 16); \
} while (0)

    const int warp_m = wid & 3;    // 0..3 -> 32 rows each
    const int warp_n = wid >> 2;   // 0..1 -> 64 cols each

    // ldmatrix lane address components
    const int a_row = lane & 15, a_chunk = lane >> 4;              // A: rows 0..15, chunk 0/1
    const int b_row = ((lane >> 4) << 3) + (lane & 7);             // B: n 0..15 pattern
    const int b_chunk = (lane >> 3) & 1;

    float acc[2][8][4];
    #pragma unroll
    for (int i = 0; i < 2; i++)
        #pragma unroll
        for (int j = 0; j < 8; j++)
            #pragma unroll
            for (int k = 0; k < 4; k++) acc[i][j][k] = 0.f;

    // prologue: stages 0,1
    LOAD_STAGE(0, 0); CP_COMMIT();
    LOAD_STAGE(1, 1); CP_COMMIT();

    const int KT = D_DIM / BK;   // 64
    for (int kt = 0; kt < KT; kt++) {
        CP_WAIT(1);
        __syncthreads();
        if (kt + 2 < KT) LOAD_STAGE((kt + 2) % NSTAGE, kt + 2);
        CP_COMMIT();

        const uint32_t Ab = sb + (kt % NSTAGE) * STG_BYTES;
        const uint32_t Bb = Ab + ATILE;
        #pragma unroll
        for (int ks = 0; ks < 2; ks++) {
            uint32_t a[2][4], b[4][4];
            #pragma unroll
            for (int mi = 0; mi < 2; mi++)
                ldsm4(a[mi], Ab + (uint32_t)(warp_m * 32 + mi * 16 + a_row) * ROWSTR
                               + (uint32_t)(ks * 2 + a_chunk) * 16);
            #pragma unroll
            for (int nb = 0; nb < 4; nb++)
                ldsm4(b[nb], Bb + (uint32_t)(warp_n * 64 + nb * 16 + b_row) * ROWSTR
                               + (uint32_t)(ks * 2 + b_chunk) * 16);
            #pragma unroll
            for (int mi = 0; mi < 2; mi++)
                #pragma unroll
                for (int n8 = 0; n8 < 8; n8++)
                    mma16816(acc[mi][n8], a[mi], b[n8 >> 1][(n8 & 1) * 2],
                             b[n8 >> 1][(n8 & 1) * 2 + 1]);
        }
        // No trailing sync needed: next overwrite of this slot is issued only
        // after the next iteration's CP_WAIT + __syncthreads.
    }
    CP_WAIT(0);
    __syncthreads();

    // epilogue: stage bf16 tile in smem (stride 136 elems = 272B), then 16B stores
    #pragma unroll
    for (int mi = 0; mi < 2; mi++)
        #pragma unroll
        for (int n8 = 0; n8 < 8; n8++) {
            int mr = warp_m * 32 + mi * 16 + (lane >> 2);
            int nc = warp_n * 64 + n8 * 8 + 2 * (lane & 3);
            uint32_t p0 = pack_bf2(acc[mi][n8][0], acc[mi][n8][1]);
            uint32_t p1 = pack_bf2(acc[mi][n8][2], acc[mi][n8][3]);
            asm volatile("st.shared.b32 [%0], %1;" ::
                "r"(sb + (uint32_t)(mr * 136 + nc) * 2), "r"(p0) : "memory");
            asm volatile("st.shared.b32 [%0], %1;" ::
                "r"(sb + (uint32_t)((mr + 8) * 136 + nc) * 2), "r"(p1) : "memory");
        }
    __syncthreads();
    #pragma unroll
    for (int it = 0; it < 8; it++) {
        int idx = tid + it * 256;          // 2048 x 16B
        int r = idx >> 4, seg = idx & 15;
        uint4 v;
        asm volatile("ld.shared.v4.u32 {%0,%1,%2,%3}, [%4];"
            : "=r"(v.x), "=r"(v.y), "=r"(v.z), "=r"(v.w)
            : "r"(sb + (uint32_t)(r * 272 + seg * 16)));
        *reinterpret_cast<uint4*>(
            g_sim + (size_t)(mt * BM + r) * KEMB + (size_t)nt * BN + seg * 8) = v;
    }
#undef LOAD_STAGE
}

// ---------------------------------------------------------------------------
// reduce: per row, approx max over bf16 sims, collect candidates within DELTA,
// rescore each in exact fp32, first-occurrence tie-break. grid = NPIX, 256 thr.
// ---------------------------------------------------------------------------
#define DELTA 0.03f
#define MAXCAND 512
__global__ void __launch_bounds__(256) reduce_kernel() {
    const int n = blockIdx.x, tid = threadIdx.x;
    const int lane = tid & 31, w = tid >> 5;
    const uint4* sp = reinterpret_cast<const uint4*>(g_sim + (size_t)n * KEMB);

    uint4 v[8];
    float lmax = -1e30f;
    #pragma unroll
    for (int i = 0; i < 8; i++) {
        v[i] = sp[tid + i * 256];
        const uint32_t* u = reinterpret_cast<const uint32_t*>(&v[i]);
        #pragma unroll
        for (int q = 0; q < 4; q++)
            lmax = fmaxf(lmax, fmaxf(bflo(u[q]), bfhi(u[q])));
    }

    __shared__ float swarp[8];
    __shared__ float sbc;
    __shared__ int scnt;
    __shared__ int slist[MAXCAND];
    if (tid == 0) scnt = 0;
    #pragma unroll
    for (int o = 16; o; o >>= 1) lmax = fmaxf(lmax, __shfl_xor_sync(0xffffffffu, lmax, o));
    if (lane == 0) swarp[w] = lmax;
    __syncthreads();
    if (tid == 0) {
        float m = swarp[0];
        #pragma unroll
        for (int i = 1; i < 8; i++) m = fmaxf(m, swarp[i]);
        sbc = m;
    }
    __syncthreads();
    const float thr = sbc - DELTA;

    #pragma unroll
    for (int i = 0; i < 8; i++) {
        const uint32_t* u = reinterpret_cast<const uint32_t*>(&v[i]);
        int kbase = (tid + i * 256) * 8;
        #pragma unroll
        for (int q = 0; q < 4; q++) {
            float a = bflo(u[q]), b = bfhi(u[q]);
            if (a >= thr) { int p = atomicAdd(&scnt, 1); if (p < MAXCAND) slist[p] = kbase + q * 2; }
            if (b >= thr) { int p = atomicAdd(&scnt, 1); if (p < MAXCAND) slist[p] = kbase + q * 2 + 1; }
        }
    }
    __syncthreads();
    const int cnt = scnt < MAXCAND ? scnt : MAXCAND;

    float best = -1e30f;
    int bidx = 0x7fffffff;
    const float4* zp = reinterpret_cast<const float4*>(g_zT + (size_t)n * D_DIM);
    float4 a0 = zp[2 * tid], a1 = zp[2 * tid + 1];
    for (int ci = 0; ci < cnt; ci++) {
        const int idx = slist[ci];
        const float4* ep = reinterpret_cast<const float4*>(g_e_n + (size_t)idx * D_DIM);
        float4 b0 = ep[2 * tid], b1 = ep[2 * tid + 1];
        float s = a0.x*b0.x + a0.y*b0.y + a0.z*b0.z + a0.w*b0.w
                + a1.x*b1.x + a1.y*b1.y + a1.z*b1.z + a1.w*b1.w;
        #pragma unroll
        for (int o = 16; o; o >>= 1) s += __shfl_xor_sync(0xffffffffu, s, o);
        if (lane == 0) swarp[w] = s;
        __syncthreads();
        if (tid == 0) {
            float t = 0.f;
            #pragma unroll
            for (int i = 0; i < 8; i++) t += swarp[i];
            if (t > best || (t == best && idx < bidx)) { best = t; bidx = idx; }
        }
        __syncthreads();
    }
    if (tid == 0) g_idx[n] = bidx;
}

// ---------------------------------------------------------------------------
// gather: quant = e_n[idx] back to (B,C,H,W); optional idx tail.
// ---------------------------------------------------------------------------
__global__ void gather_kernel(float* __restrict__ out, int write_idx_tail) {
    const int b = blockIdx.x >> 5;
    const int h = blockIdx.x & 31;
    const int tid = threadIdx.x;
    const int w = tid & 31;
    const int q = tid >> 5;
    __shared__ int rowidx[32];
    __shared__ float tile[32][33];

    if (tid < 32) {
        int n = (b * 32 + h) * 32 + tid;
        int id = g_idx[n];
        rowidx[tid] = id;
        if (write_idx_tail) out[QUANT_ELEMS + n] = (float)id;
    }
    __syncthreads();

    for (int c0 = 0; c0 < D_DIM; c0 += 32) {
        #pragma unroll
        for (int j = 0; j < 4; j++) {
            int c = c0 + q + 8 * j;
            tile[q + 8 * j][w] = g_e_n[(size_t)rowidx[w] * D_DIM + c];
        }
        __syncthreads();
        #pragma unroll
        for (int j = 0; j < 4; j++) {
            int c = c0 + q + 8 * j;
            out[(((size_t)b * D_DIM + c) * 32 + h) * 32 + w] = tile[q + 8 * j][w];
        }
        __syncthreads();
    }
}

__global__ void idx_only_kernel(int* __restrict__ out) {
    int n = blockIdx.x * 256 + threadIdx.x;
    if (n < NPIX) out[n] = g_idx[n];
}

// ---------------------------------------------------------------------------
extern "C" void kernel_launch(void* const* d_in, const int* in_sizes, int n_in,
                              void* d_out, int out_size) {
    const float* hidden = (const float*)d_in[0];
    const float* embed  = (const float*)d_in[1];
    if (n_in >= 2 && in_sizes[0] == KEMB * D_DIM) {
        const float* t = hidden; hidden = embed; embed = t;
    }

    static int smem_set = 0;
    if (!smem_set) {
        cudaFuncSetAttribute(gemm_kernel, cudaFuncAttributeMaxDynamicSharedMemorySize, GEMM_SMEM);
        smem_set = 1;
    }

    prep_e_kernel<<<KEMB, 256>>>(embed);
    prep_z_kernel<<<256, 256>>>(hidden);

    dim3 grid(NPIX / BM, KEMB / BN);   // (64, 128)
    gemm_kernel<<<grid, 256, GEMM_SMEM>>>();

    reduce_kernel<<<NPIX, 256>>>();

    if (out_size == NPIX) {
        idx_only_kernel<<<(NPIX + 255) / 256, 256>>>((int*)d_out);
    } else {
        int tail = (out_size >= QUANT_ELEMS + NPIX) ? 1 : 0;
        gather_kernel<<<256, 256>>>((float*)d_out, tail);
    }
}